// round 16
// baseline (speedup 1.0000x reference)
#include <cuda_runtime.h>
#include <cuda_bf16.h>
#include <cstdint>
#include <cstddef>

typedef __nv_bfloat16 bf16;

#define B_ 64
#define T_ 256
#define I_ 256
#define H_ 1024
#define C_ 1000
#define NG 4096  /* 4*H gate columns, col = 4*h + g */
#define NCTA 128

// ---------------- device scratch (static, no allocations) ----------------
__device__ float g_Z0x[(size_t)T_ * B_ * NG];                 // x@W0x + b0, [t][b][4h+g]
__device__ bf16  g_Axhi[NG * I_],            g_Axlo[NG * I_];
__device__ bf16  g_A0hi[(size_t)NG * H_],    g_A0lo[(size_t)NG * H_];
__device__ bf16  g_A1hi[(size_t)NG * 2*H_],  g_A1lo[(size_t)NG * 2*H_];
__device__ bf16  g_xhi[(size_t)T_ * B_ * I_], g_xlo[(size_t)T_ * B_ * I_];
// h ping-pong by time parity: [par][b*H + h]
__device__ bf16  g_h0hi[2][B_ * H_], g_h0lo[2][B_ * H_];
__device__ bf16  g_h1hi[2][B_ * H_], g_h1lo[2][B_ * H_];
__device__ float g_h1f[B_ * H_];
__device__ unsigned g_bar;

// ---------------- merged prep: init + weight transpose/split + x split ----------------
__global__ __launch_bounds__(256) void prep_kernel(
    const float* __restrict__ x,
    const float* __restrict__ W0x, const float* __restrict__ W0h,
    const float* __restrict__ W1x, const float* __restrict__ W1h)
{
    __shared__ float ts[8][32][33];
    const int blk = blockIdx.x;
    if (blk < 512) {
        int idx = blk * 256 + threadIdx.x;
        if (idx == 0) g_bar = 0;
        if (idx < 2 * B_ * H_) {
            bf16 z = __float2bfloat16(0.f);
            ((bf16*)g_h0hi)[idx] = z; ((bf16*)g_h0lo)[idx] = z;
            ((bf16*)g_h1hi)[idx] = z; ((bf16*)g_h1lo)[idx] = z;
        }
        return;
    }
    if (blk < 2176) {
        int wt = (blk - 512) * 8 + (threadIdx.x >> 5);
        int lane = threadIdx.x & 31;
        const float* W; bf16 *hi, *lo; int Ksrc, Ktot, koff, tk;
        if (wt < 1024)      { W = W0x; hi = g_Axhi; lo = g_Axlo; Ksrc = I_; Ktot = I_;     koff = 0;  tk = 8;  }
        else if (wt < 5120) { W = W0h; hi = g_A0hi; lo = g_A0lo; Ksrc = H_; Ktot = H_;     koff = 0;  tk = 32; wt -= 1024; }
        else if (wt < 9216) { W = W1x; hi = g_A1hi; lo = g_A1lo; Ksrc = H_; Ktot = 2 * H_; koff = 0;  tk = 32; wt -= 5120; }
        else                { W = W1h; hi = g_A1hi; lo = g_A1lo; Ksrc = H_; Ktot = 2 * H_; koff = H_; tk = 32; wt -= 9216; }
        int g  = wt / (tk * 32);
        int r2 = wt % (tk * 32);
        int k0 = (r2 / 32) * 32, h0 = (r2 % 32) * 32;
        float (*tile)[33] = ts[threadIdx.x >> 5];
#pragma unroll 4
        for (int r = 0; r < 32; r++)
            tile[r][lane] = W[((size_t)g * Ksrc + k0 + r) * H_ + h0 + lane];
        __syncwarp();
#pragma unroll 4
        for (int r = 0; r < 32; r++) {
            float v = tile[lane][r];                 // (k = k0+lane, h = h0+r)
            bf16 vh = __float2bfloat16(v);
            size_t di = (size_t)(4 * (h0 + r) + g) * Ktot + koff + k0 + lane;
            hi[di] = vh;
            lo[di] = __float2bfloat16(v - __bfloat162float(vh));
        }
        return;
    }
    {
        size_t idx = (size_t)(blk - 2176) * 256 + threadIdx.x;  // = (b*T + t)*I + k
        if (idx >= (size_t)B_ * T_ * I_) return;
        int k = (int)(idx % I_);
        size_t r = idx / I_;
        int t = (int)(r % T_);
        int b = (int)(r / T_);
        float v = x[idx];
        bf16 vh = __float2bfloat16(v);
        size_t di = ((size_t)t * B_ + b) * I_ + k;
        g_xhi[di] = vh;
        g_xlo[di] = __float2bfloat16(v - __bfloat162float(vh));
    }
}

__global__ void dummy_kernel() {}

__device__ __forceinline__ void mma_bf16(float d[4], const uint32_t a[4], const uint32_t b[2]) {
    asm volatile(
        "mma.sync.aligned.m16n8k16.row.col.f32.bf16.bf16.f32 "
        "{%0,%1,%2,%3}, {%4,%5,%6,%7}, {%8,%9}, {%0,%1,%2,%3};\n"
        : "+f"(d[0]), "+f"(d[1]), "+f"(d[2]), "+f"(d[3])
        : "r"(a[0]), "r"(a[1]), "r"(a[2]), "r"(a[3]), "r"(b[0]), "r"(b[1]));
}

__device__ __forceinline__ void ldsm4(uint32_t r[4], uint32_t addr) {
    asm volatile("ldmatrix.sync.aligned.m8n8.x4.shared.b16 {%0,%1,%2,%3}, [%4];"
        : "=r"(r[0]), "=r"(r[1]), "=r"(r[2]), "=r"(r[3]) : "r"(addr));
}

__device__ __forceinline__ void ldsm2(uint32_t r[2], uint32_t addr) {
    asm volatile("ldmatrix.sync.aligned.m8n8.x2.shared.b16 {%0,%1}, [%2];"
        : "=r"(r[0]), "=r"(r[1]) : "r"(addr));
}

__device__ __forceinline__ void cp16(uint32_t dst, const void* src) {
    asm volatile("cp.async.cg.shared.global [%0], [%1], 16;\n" :: "r"(dst), "l"(src));
}

// ================= prologue GEMM (x @ W0x), proven path =================
#define SMEM_BYTES 40960
#define ASTRIDE 80

__device__ __forceinline__ void mma_tile(const bf16* As_hi, const bf16* As_lo,
                                         const bf16* Bs_hi, const bf16* Bs_lo,
                                         float acc[4][4],
                                         int wm, int wn, int grp, int tig) {
#pragma unroll
    for (int kk = 0; kk < 64; kk += 16) {
        uint32_t ah[2][4], al[2][4], bh[2][2], bl[2][2];
#pragma unroll
        for (int mi = 0; mi < 2; mi++) {
            int base = (wm * 32 + mi * 16 + grp) * ASTRIDE + kk + tig * 2;
            ah[mi][0] = *(const uint32_t*)&As_hi[base];
            ah[mi][1] = *(const uint32_t*)&As_hi[base + 8 * ASTRIDE];
            ah[mi][2] = *(const uint32_t*)&As_hi[base + 8];
            ah[mi][3] = *(const uint32_t*)&As_hi[base + 8 * ASTRIDE + 8];
            al[mi][0] = *(const uint32_t*)&As_lo[base];
            al[mi][1] = *(const uint32_t*)&As_lo[base + 8 * ASTRIDE];
            al[mi][2] = *(const uint32_t*)&As_lo[base + 8];
            al[mi][3] = *(const uint32_t*)&As_lo[base + 8 * ASTRIDE + 8];
        }
#pragma unroll
        for (int ni = 0; ni < 2; ni++) {
            int base = (wn * 16 + ni * 8 + grp) * ASTRIDE + kk + tig * 2;
            bh[ni][0] = *(const uint32_t*)&Bs_hi[base];
            bh[ni][1] = *(const uint32_t*)&Bs_hi[base + 8];
            bl[ni][0] = *(const uint32_t*)&Bs_lo[base];
            bl[ni][1] = *(const uint32_t*)&Bs_lo[base + 8];
        }
#pragma unroll
        for (int mi = 0; mi < 2; mi++)
#pragma unroll
            for (int ni = 0; ni < 2; ni++) {
                mma_bf16(acc[mi * 2 + ni], ah[mi], bh[ni]);
                mma_bf16(acc[mi * 2 + ni], al[mi], bh[ni]);
                mma_bf16(acc[mi * 2 + ni], ah[mi], bl[ni]);
            }
    }
}

__global__ __launch_bounds__(256) void gemm_x_kernel(const float* __restrict__ b0) {
    __shared__ __align__(16) char sm[SMEM_BYTES];
    bf16* As_hi = (bf16*)(sm);
    bf16* As_lo = (bf16*)(sm + 10240);
    bf16* Bs_hi = (bf16*)(sm + 20480);
    bf16* Bs_lo = (bf16*)(sm + 30720);
    int t = blockIdx.y, nb = blockIdx.x;
    const bf16* Ahi = g_xhi + (size_t)t * B_ * I_;
    const bf16* Alo = g_xlo + (size_t)t * B_ * I_;
    const bf16* Bhi = g_Axhi + (size_t)nb * 64 * I_;
    const bf16* Blo = g_Axlo + (size_t)nb * 64 * I_;
    float acc[4][4] = {};
    const int tid  = threadIdx.x;
    const int lane = tid & 31;
    const int warp = tid >> 5;
    const int wm = warp >> 2, wn = warp & 3;
    const int grp = lane >> 2, tig = lane & 3;
    const int lrow = tid >> 2;
    const int lcg  = (tid & 3) << 4;
    for (int k0 = 0; k0 < I_; k0 += 64) {
        __syncthreads();
        *(uint4*)&As_hi[lrow * ASTRIDE + lcg]     = *(const uint4*)(Ahi + (size_t)lrow * I_ + k0 + lcg);
        *(uint4*)&As_hi[lrow * ASTRIDE + lcg + 8] = *(const uint4*)(Ahi + (size_t)lrow * I_ + k0 + lcg + 8);
        *(uint4*)&As_lo[lrow * ASTRIDE + lcg]     = *(const uint4*)(Alo + (size_t)lrow * I_ + k0 + lcg);
        *(uint4*)&As_lo[lrow * ASTRIDE + lcg + 8] = *(const uint4*)(Alo + (size_t)lrow * I_ + k0 + lcg + 8);
        *(uint4*)&Bs_hi[lrow * ASTRIDE + lcg]     = *(const uint4*)(Bhi + (size_t)lrow * I_ + k0 + lcg);
        *(uint4*)&Bs_hi[lrow * ASTRIDE + lcg + 8] = *(const uint4*)(Bhi + (size_t)lrow * I_ + k0 + lcg + 8);
        *(uint4*)&Bs_lo[lrow * ASTRIDE + lcg]     = *(const uint4*)(Blo + (size_t)lrow * I_ + k0 + lcg);
        *(uint4*)&Bs_lo[lrow * ASTRIDE + lcg + 8] = *(const uint4*)(Blo + (size_t)lrow * I_ + k0 + lcg + 8);
        __syncthreads();
        mma_tile(As_hi, As_lo, Bs_hi, Bs_lo, acc, wm, wn, grp, tig);
    }
#pragma unroll
    for (int mi = 0; mi < 2; mi++)
#pragma unroll
        for (int ni = 0; ni < 2; ni++) {
            float* d = acc[mi * 2 + ni];
            int r = wm * 32 + mi * 16 + grp;
            int c = wn * 16 + ni * 8 + tig * 2;
#pragma unroll
            for (int e = 0; e < 4; e++) {
                int rr = r + ((e >= 2) ? 8 : 0);
                int colg = nb * 64 + c + (e & 1);
                g_Z0x[(size_t)(t * 64 + rr) * NG + colg] = d[e] + b0[(colg & 3) * H_ + (colg >> 2)];
            }
        }
}

// ================= persistent wavefront recurrence =================
// 128 CTAs, 1/SM, 512 threads (16 warps; warp tile 16m x 8n). Per tick, CTA nb:
//   iters [0,16):  A = h0(tick-1) chunk (shared), B0 + B1(first-half); mma into a0 AND a1
//   iters [16,32): A = h1(tick-2) chunk, B1(second-half); mma into a1
// 5-stage cp.async pipeline, prefetch distance 4, wait_group 3.
// Stage (36864 B): Ahi[0) Alo[9216) B0h[18432) B0l[23040) B1h[27648) B1l[32256).
#define NSTAGE 5
#define PSTG 36864
#define PAS 72

__global__ void __launch_bounds__(512, 1) lstm_persist(const float* __restrict__ b1) {
    extern __shared__ __align__(16) char sm[];
    const int tid  = threadIdx.x;
    const int lane = tid & 31;
    const int warp = tid >> 5;
    const int wm = warp >> 2;           // 0..3 -> m = wm*16
    const int wn = warp & 3;            // 0..3 -> n = wn*8
    const int nb = blockIdx.x;

    const uint32_t smb = (uint32_t)__cvta_generic_to_shared(sm);
    const int gq = lane >> 3, jq = lane & 7;
    const uint32_t aA  = (uint32_t)(((wm * 16 + (gq & 1) * 8 + jq) * PAS + (gq >> 1) * 8) * 2);
    const uint32_t aB0 = 18432u + (uint32_t)(((wn * 8 + jq) * PAS + (gq & 1) * 8) * 2);
    const uint32_t aB1 = aB0 + 9216u;

    // loader mapping (512 threads)
    const int lr = tid >> 3;            // A row 0..63 (batch)
    const int lc = (tid & 7) * 8;       // A col (bf16): one 16B chunk
    const uint32_t dAh = (uint32_t)((lr * PAS + lc) * 2);
    const uint32_t dAl = dAh + 9216;
    const int arow = lr * H_ + lc;
    const bool half0 = (tid < 256);     // threads 0-255: B0; 256-511: B1
    const int br = (tid & 255) >> 3;    // B row 0..31 (gate col)
    const int bc = (tid & 7) * 8;
    const uint32_t dB = (uint32_t)(18432 + (br * PAS + bc) * 2);  // B0h dest base
    const bf16* W0bh = g_A0hi + (size_t)(nb * 32 + br) * H_ + bc;
    const bf16* W0bl = g_A0lo + (size_t)(nb * 32 + br) * H_ + bc;
    const bf16* W1bh = g_A1hi + (size_t)(nb * 32 + br) * (2 * H_) + bc;
    const bf16* W1bl = g_A1lo + (size_t)(nb * 32 + br) * (2 * H_) + bc;

    // epilogue: each thread owns one (b, hl) per layer
    const int hl = tid & 7, bep = tid >> 3;   // bep 0..63
    const int hg = nb * 8 + hl;
    float c0reg = 0.f, c1reg = 0.f;
    const float bz0 = b1[hg], bz1 = b1[H_ + hg], bz2 = b1[2 * H_ + hg], bz3 = b1[3 * H_ + hg];

    for (int tick = 0; tick <= T_; tick++) {
        const int  w0   = tick & 1;                 // L0 writes h0[w0]; L1 writes h1[w0^1]
        const bool doL0 = (tick < T_);
        const bool doL1 = (tick >= 1);
        const int  itE  = doL1 ? 32 : 16;
        const bf16* hRh  = g_h0hi[w0 ^ 1];          // h0(tick-1)
        const bf16* hRl  = g_h0lo[w0 ^ 1];
        const bf16* h1Rh = g_h1hi[w0];              // h1(tick-2)
        const bf16* h1Rl = g_h1lo[w0];

        auto issue = [&](int it, int stg) {
            uint32_t st = smb + (uint32_t)stg * PSTG;
            if (it < 16) {
                int kk = it * 64;
                cp16(st + dAh, hRh + arow + kk);
                cp16(st + dAl, hRl + arow + kk);
                if (half0) { if (doL0) { cp16(st + dB, W0bh + kk);          cp16(st + dB + 4608, W0bl + kk); } }
                else       { if (doL1) { cp16(st + dB + 9216, W1bh + kk);   cp16(st + dB + 13824, W1bl + kk); } }
            } else {
                int kk = (it - 16) * 64;
                cp16(st + dAh, h1Rh + arow + kk);
                cp16(st + dAl, h1Rl + arow + kk);
                if (!half0) { cp16(st + dB + 9216, W1bh + H_ + kk); cp16(st + dB + 13824, W1bl + H_ + kk); }
            }
        };

        // pipeline prologue: 4 groups ahead
#pragma unroll
        for (int j = 0; j < 4; j++) { issue(j, j); asm volatile("cp.async.commit_group;\n"); }

        // early prefetch of L0 epilogue operand (DRAM-resident Z0x)
        float4 zx0;
        if (doL0)
            zx0 = *(const float4*)&g_Z0x[((size_t)tick * 64 + bep) * NG + nb * 32 + hl * 4];

        float a0[4] = {}, a1[4] = {};
        int s = 0, sn = 4;
        for (int it = 0; it < itE; it++) {
            asm volatile("cp.async.wait_group 3;\n");
            __syncthreads();                        // stage s (iter it) ready
            int nx = it + 4;
            if (nx < itE) issue(nx, sn);
            asm volatile("cp.async.commit_group;\n");
            const uint32_t st = smb + (uint32_t)s * PSTG;
            if (it < 16) {
#pragma unroll
                for (int kk = 0; kk < 64; kk += 16) {
                    uint32_t ah[4], al[4];
                    ldsm4(ah, st + aA + kk * 2);
                    ldsm4(al, st + aA + 9216 + kk * 2);
                    if (doL0) {
                        uint32_t bh[2], bl[2];
                        ldsm2(bh, st + aB0 + kk * 2);
                        ldsm2(bl, st + aB0 + 4608 + kk * 2);
                        mma_bf16(a0, ah, bh); mma_bf16(a0, al, bh); mma_bf16(a0, ah, bl);
                    }
                    if (doL1) {
                        uint32_t bh[2], bl[2];
                        ldsm2(bh, st + aB1 + kk * 2);
                        ldsm2(bl, st + aB1 + 4608 + kk * 2);
                        mma_bf16(a1, ah, bh); mma_bf16(a1, al, bh); mma_bf16(a1, ah, bl);
                    }
                }
            } else {
#pragma unroll
                for (int kk = 0; kk < 64; kk += 16) {
                    uint32_t ah[4], al[4], bh[2], bl[2];
                    ldsm4(ah, st + aA + kk * 2);
                    ldsm4(al, st + aA + 9216 + kk * 2);
                    ldsm2(bh, st + aB1 + kk * 2);
                    ldsm2(bl, st + aB1 + 4608 + kk * 2);
                    mma_bf16(a1, ah, bh); mma_bf16(a1, al, bh); mma_bf16(a1, ah, bl);
                }
            }
            s  = (s == NSTAGE - 1) ? 0 : s + 1;
            sn = (sn == NSTAGE - 1) ? 0 : sn + 1;
        }
        __syncthreads();

        // park both z tiles (64x32 each) so each thread gathers all 4 gates of one (b,h)
        float* z0 = (float*)sm;
        float* z1 = (float*)(sm + 8448);
        {
            int r = wm * 16 + (lane >> 2), c = wn * 8 + (lane & 3) * 2;
            z0[r * 33 + c]           = a0[0]; z0[r * 33 + c + 1]       = a0[1];
            z0[(r + 8) * 33 + c]     = a0[2]; z0[(r + 8) * 33 + c + 1] = a0[3];
            z1[r * 33 + c]           = a1[0]; z1[r * 33 + c + 1]       = a1[1];
            z1[(r + 8) * 33 + c]     = a1[2]; z1[(r + 8) * 33 + c + 1] = a1[3];
        }
        __syncthreads();

        if (doL0) {   // L0 epilogue: t = tick, write h0[w0]
            float zg = z0[bep * 33 + hl * 4 + 0] + zx0.x;
            float zi = z0[bep * 33 + hl * 4 + 1] + zx0.y;
            float zf = z0[bep * 33 + hl * 4 + 2] + zx0.z;
            float zo = z0[bep * 33 + hl * 4 + 3] + zx0.w;
            float gt = tanhf(zg);
            float ig = 1.f / (1.f + __expf(-zi));
            float fg = 1.f / (1.f + __expf(-zf));
            float og = 1.f / (1.f + __expf(-zo));
            float cn = gt * ig + c0reg * fg;
            c0reg = cn;
            float hn = tanhf(cn) * og;
            bf16 hh = __float2bfloat16(hn);
            g_h0hi[w0][bep * H_ + hg] = hh;
            g_h0lo[w0][bep * H_ + hg] = __float2bfloat16(hn - __bfloat162float(hh));
        }
        if (doL1) {   // L1 epilogue: t' = tick-1, write h1[w0^1]
            float zg = z1[bep * 33 + hl * 4 + 0] + bz0;
            float zi = z1[bep * 33 + hl * 4 + 1] + bz1;
            float zf = z1[bep * 33 + hl * 4 + 2] + bz2;
            float zo = z1[bep * 33 + hl * 4 + 3] + bz3;
            float gt = tanhf(zg);
            float ig = 1.f / (1.f + __expf(-zi));
            float fg = 1.f / (1.f + __expf(-zf));
            float og = 1.f / (1.f + __expf(-zo));
            float cn = gt * ig + c1reg * fg;
            c1reg = cn;
            float hn = tanhf(cn) * og;
            bf16 hh = __float2bfloat16(hn);
            g_h1hi[w0 ^ 1][bep * H_ + hg] = hh;
            g_h1lo[w0 ^ 1][bep * H_ + hg] = __float2bfloat16(hn - __bfloat162float(hh));
            if (tick - 1 == T_ - 1) g_h1f[bep * H_ + hg] = hn;
        }

        // ---- global barrier (monotonic counter; zeroed by prep each launch) ----
        __syncthreads();
        if (tid == 0) {
            __threadfence();
            atomicAdd(&g_bar, 1u);
            unsigned target = (unsigned)(tick + 1) * NCTA;
            while (*((volatile unsigned*)&g_bar) < target) __nanosleep(32);
            __threadfence();
        }
        __syncthreads();
    }
}

// out = h1(T-1) @ Wo + bo   (one block per batch row)
__global__ __launch_bounds__(256) void out_kernel(const float* __restrict__ Wo,
                                                  const float* __restrict__ bo,
                                                  float* __restrict__ out) {
    __shared__ float hs[H_];
    int b = blockIdx.x;
    for (int k = threadIdx.x; k < H_; k += 256) hs[k] = g_h1f[b * H_ + k];
    __syncthreads();
    for (int c = threadIdx.x; c < C_; c += 256) {
        float a = bo[c];
#pragma unroll 8
        for (int k = 0; k < H_; k++) a += hs[k] * Wo[k * C_ + c];
        out[b * C_ + c] = a;
    }
}

extern "C" void kernel_launch(void* const* d_in, const int* in_sizes, int n_in,
                              void* d_out, int out_size) {
    const float* x   = (const float*)d_in[0];
    const float* W0x = (const float*)d_in[1];
    const float* W0h = (const float*)d_in[2];
    const float* b0  = (const float*)d_in[3];
    const float* W1x = (const float*)d_in[4];
    const float* W1h = (const float*)d_in[5];
    const float* b1  = (const float*)d_in[6];
    const float* Wo  = (const float*)d_in[7];
    const float* bo  = (const float*)d_in[8];
    float* out = (float*)d_out;

    cudaFuncSetAttribute(lstm_persist, cudaFuncAttributeMaxDynamicSharedMemorySize,
                         NSTAGE * PSTG);

    // lstm_persist stays our 4th launch (ncu -s 5 -c 1 captures it)
    prep_kernel<<<18560, 256>>>(x, W0x, W0h, W1x, W1h);          // #1
    {
        dim3 g(NG / 64, T_);
        gemm_x_kernel<<<g, 256>>>(b0);                           // #2
    }
    dummy_kernel<<<1, 32>>>();                                   // #3
    lstm_persist<<<NCTA, 512, NSTAGE * PSTG>>>(b1);              // #4  <- profiled
    out_kernel<<<B_, 256>>>(Wo, bo, out);                        // #5
}

// round 17
// speedup vs baseline: 1.0509x; 1.0509x over previous
#include <cuda_runtime.h>
#include <cuda_bf16.h>
#include <cstdint>
#include <cstddef>

typedef __nv_bfloat16 bf16;

#define B_ 64
#define T_ 256
#define I_ 256
#define H_ 1024
#define C_ 1000
#define NG 4096  /* 4*H gate columns, col = 4*h + g */
#define NCTA 128

// ---------------- device scratch (static, no allocations) ----------------
__device__ float g_Z0x[(size_t)T_ * B_ * NG];                 // x@W0x + b0, [t][b][4h+g]
__device__ bf16  g_Axhi[NG * I_],            g_Axlo[NG * I_];
__device__ bf16  g_A0hi[(size_t)NG * H_],    g_A0lo[(size_t)NG * H_];
__device__ bf16  g_A1hi[(size_t)NG * 2*H_],  g_A1lo[(size_t)NG * 2*H_];
__device__ bf16  g_xhi[(size_t)T_ * B_ * I_], g_xlo[(size_t)T_ * B_ * I_];
// h ping-pong by time parity: [par][b*H + h]
__device__ bf16  g_h0hi[2][B_ * H_], g_h0lo[2][B_ * H_];
__device__ bf16  g_h1hi[2][B_ * H_], g_h1lo[2][B_ * H_];
__device__ float g_h1f[B_ * H_];
__device__ unsigned g_bar;

// ---------------- merged prep: init + weight transpose/split + x split ----------------
__global__ __launch_bounds__(256) void prep_kernel(
    const float* __restrict__ x,
    const float* __restrict__ W0x, const float* __restrict__ W0h,
    const float* __restrict__ W1x, const float* __restrict__ W1h)
{
    __shared__ float ts[8][32][33];
    const int blk = blockIdx.x;
    if (blk < 512) {
        int idx = blk * 256 + threadIdx.x;
        if (idx == 0) g_bar = 0;
        if (idx < 2 * B_ * H_) {
            bf16 z = __float2bfloat16(0.f);
            ((bf16*)g_h0hi)[idx] = z; ((bf16*)g_h0lo)[idx] = z;
            ((bf16*)g_h1hi)[idx] = z; ((bf16*)g_h1lo)[idx] = z;
        }
        return;
    }
    if (blk < 2176) {
        int wt = (blk - 512) * 8 + (threadIdx.x >> 5);
        int lane = threadIdx.x & 31;
        const float* W; bf16 *hi, *lo; int Ksrc, Ktot, koff, tk;
        if (wt < 1024)      { W = W0x; hi = g_Axhi; lo = g_Axlo; Ksrc = I_; Ktot = I_;     koff = 0;  tk = 8;  }
        else if (wt < 5120) { W = W0h; hi = g_A0hi; lo = g_A0lo; Ksrc = H_; Ktot = H_;     koff = 0;  tk = 32; wt -= 1024; }
        else if (wt < 9216) { W = W1x; hi = g_A1hi; lo = g_A1lo; Ksrc = H_; Ktot = 2 * H_; koff = 0;  tk = 32; wt -= 5120; }
        else                { W = W1h; hi = g_A1hi; lo = g_A1lo; Ksrc = H_; Ktot = 2 * H_; koff = H_; tk = 32; wt -= 9216; }
        int g  = wt / (tk * 32);
        int r2 = wt % (tk * 32);
        int k0 = (r2 / 32) * 32, h0 = (r2 % 32) * 32;
        float (*tile)[33] = ts[threadIdx.x >> 5];
#pragma unroll 4
        for (int r = 0; r < 32; r++)
            tile[r][lane] = W[((size_t)g * Ksrc + k0 + r) * H_ + h0 + lane];
        __syncwarp();
#pragma unroll 4
        for (int r = 0; r < 32; r++) {
            float v = tile[lane][r];                 // (k = k0+lane, h = h0+r)
            bf16 vh = __float2bfloat16(v);
            size_t di = (size_t)(4 * (h0 + r) + g) * Ktot + koff + k0 + lane;
            hi[di] = vh;
            lo[di] = __float2bfloat16(v - __bfloat162float(vh));
        }
        return;
    }
    {
        size_t idx = (size_t)(blk - 2176) * 256 + threadIdx.x;  // = (b*T + t)*I + k
        if (idx >= (size_t)B_ * T_ * I_) return;
        int k = (int)(idx % I_);
        size_t r = idx / I_;
        int t = (int)(r % T_);
        int b = (int)(r / T_);
        float v = x[idx];
        bf16 vh = __float2bfloat16(v);
        size_t di = ((size_t)t * B_ + b) * I_ + k;
        g_xhi[di] = vh;
        g_xlo[di] = __float2bfloat16(v - __bfloat162float(vh));
    }
}

__global__ void dummy_kernel() {}

__device__ __forceinline__ void mma_bf16(float d[4], const uint32_t a[4], const uint32_t b[2]) {
    asm volatile(
        "mma.sync.aligned.m16n8k16.row.col.f32.bf16.bf16.f32 "
        "{%0,%1,%2,%3}, {%4,%5,%6,%7}, {%8,%9}, {%0,%1,%2,%3};\n"
        : "+f"(d[0]), "+f"(d[1]), "+f"(d[2]), "+f"(d[3])
        : "r"(a[0]), "r"(a[1]), "r"(a[2]), "r"(a[3]), "r"(b[0]), "r"(b[1]));
}

__device__ __forceinline__ void ldsm4(uint32_t r[4], uint32_t addr) {
    asm volatile("ldmatrix.sync.aligned.m8n8.x4.shared.b16 {%0,%1,%2,%3}, [%4];"
        : "=r"(r[0]), "=r"(r[1]), "=r"(r[2]), "=r"(r[3]) : "r"(addr));
}

__device__ __forceinline__ void ldsm2(uint32_t r[2], uint32_t addr) {
    asm volatile("ldmatrix.sync.aligned.m8n8.x2.shared.b16 {%0,%1}, [%2];"
        : "=r"(r[0]), "=r"(r[1]) : "r"(addr));
}

__device__ __forceinline__ void cp16(uint32_t dst, const void* src) {
    asm volatile("cp.async.cg.shared.global [%0], [%1], 16;\n" :: "r"(dst), "l"(src));
}

// ================= prologue GEMM (x @ W0x), proven path =================
#define SMEM_BYTES 40960
#define ASTRIDE 80

__device__ __forceinline__ void mma_tile(const bf16* As_hi, const bf16* As_lo,
                                         const bf16* Bs_hi, const bf16* Bs_lo,
                                         float acc[4][4],
                                         int wm, int wn, int grp, int tig) {
#pragma unroll
    for (int kk = 0; kk < 64; kk += 16) {
        uint32_t ah[2][4], al[2][4], bh[2][2], bl[2][2];
#pragma unroll
        for (int mi = 0; mi < 2; mi++) {
            int base = (wm * 32 + mi * 16 + grp) * ASTRIDE + kk + tig * 2;
            ah[mi][0] = *(const uint32_t*)&As_hi[base];
            ah[mi][1] = *(const uint32_t*)&As_hi[base + 8 * ASTRIDE];
            ah[mi][2] = *(const uint32_t*)&As_hi[base + 8];
            ah[mi][3] = *(const uint32_t*)&As_hi[base + 8 * ASTRIDE + 8];
            al[mi][0] = *(const uint32_t*)&As_lo[base];
            al[mi][1] = *(const uint32_t*)&As_lo[base + 8 * ASTRIDE];
            al[mi][2] = *(const uint32_t*)&As_lo[base + 8];
            al[mi][3] = *(const uint32_t*)&As_lo[base + 8 * ASTRIDE + 8];
        }
#pragma unroll
        for (int ni = 0; ni < 2; ni++) {
            int base = (wn * 16 + ni * 8 + grp) * ASTRIDE + kk + tig * 2;
            bh[ni][0] = *(const uint32_t*)&Bs_hi[base];
            bh[ni][1] = *(const uint32_t*)&Bs_hi[base + 8];
            bl[ni][0] = *(const uint32_t*)&Bs_lo[base];
            bl[ni][1] = *(const uint32_t*)&Bs_lo[base + 8];
        }
#pragma unroll
        for (int mi = 0; mi < 2; mi++)
#pragma unroll
            for (int ni = 0; ni < 2; ni++) {
                mma_bf16(acc[mi * 2 + ni], ah[mi], bh[ni]);
                mma_bf16(acc[mi * 2 + ni], al[mi], bh[ni]);
                mma_bf16(acc[mi * 2 + ni], ah[mi], bl[ni]);
            }
    }
}

__global__ __launch_bounds__(256) void gemm_x_kernel(const float* __restrict__ b0) {
    __shared__ __align__(16) char sm[SMEM_BYTES];
    bf16* As_hi = (bf16*)(sm);
    bf16* As_lo = (bf16*)(sm + 10240);
    bf16* Bs_hi = (bf16*)(sm + 20480);
    bf16* Bs_lo = (bf16*)(sm + 30720);
    int t = blockIdx.y, nb = blockIdx.x;
    const bf16* Ahi = g_xhi + (size_t)t * B_ * I_;
    const bf16* Alo = g_xlo + (size_t)t * B_ * I_;
    const bf16* Bhi = g_Axhi + (size_t)nb * 64 * I_;
    const bf16* Blo = g_Axlo + (size_t)nb * 64 * I_;
    float acc[4][4] = {};
    const int tid  = threadIdx.x;
    const int lane = tid & 31;
    const int warp = tid >> 5;
    const int wm = warp >> 2, wn = warp & 3;
    const int grp = lane >> 2, tig = lane & 3;
    const int lrow = tid >> 2;
    const int lcg  = (tid & 3) << 4;
    for (int k0 = 0; k0 < I_; k0 += 64) {
        __syncthreads();
        *(uint4*)&As_hi[lrow * ASTRIDE + lcg]     = *(const uint4*)(Ahi + (size_t)lrow * I_ + k0 + lcg);
        *(uint4*)&As_hi[lrow * ASTRIDE + lcg + 8] = *(const uint4*)(Ahi + (size_t)lrow * I_ + k0 + lcg + 8);
        *(uint4*)&As_lo[lrow * ASTRIDE + lcg]     = *(const uint4*)(Alo + (size_t)lrow * I_ + k0 + lcg);
        *(uint4*)&As_lo[lrow * ASTRIDE + lcg + 8] = *(const uint4*)(Alo + (size_t)lrow * I_ + k0 + lcg + 8);
        *(uint4*)&Bs_hi[lrow * ASTRIDE + lcg]     = *(const uint4*)(Bhi + (size_t)lrow * I_ + k0 + lcg);
        *(uint4*)&Bs_hi[lrow * ASTRIDE + lcg + 8] = *(const uint4*)(Bhi + (size_t)lrow * I_ + k0 + lcg + 8);
        *(uint4*)&Bs_lo[lrow * ASTRIDE + lcg]     = *(const uint4*)(Blo + (size_t)lrow * I_ + k0 + lcg);
        *(uint4*)&Bs_lo[lrow * ASTRIDE + lcg + 8] = *(const uint4*)(Blo + (size_t)lrow * I_ + k0 + lcg + 8);
        __syncthreads();
        mma_tile(As_hi, As_lo, Bs_hi, Bs_lo, acc, wm, wn, grp, tig);
    }
#pragma unroll
    for (int mi = 0; mi < 2; mi++)
#pragma unroll
        for (int ni = 0; ni < 2; ni++) {
            float* d = acc[mi * 2 + ni];
            int r = wm * 32 + mi * 16 + grp;
            int c = wn * 16 + ni * 8 + tig * 2;
#pragma unroll
            for (int e = 0; e < 4; e++) {
                int rr = r + ((e >= 2) ? 8 : 0);
                int colg = nb * 64 + c + (e & 1);
                g_Z0x[(size_t)(t * 64 + rr) * NG + colg] = d[e] + b0[(colg & 3) * H_ + (colg >> 2)];
            }
        }
}

// ================= persistent wavefront recurrence =================
// 128 CTAs, 1/SM, 512 threads (16 warps; warp tile 16m x 8n).
// K=128 macro-stages: per tick 16 macro-iters (8 shared-A [h0] feeding a0+a1,
// then 8 with A=h1 feeding a1). Each stage holds two 64-K sub-chunks with the
// proven 64-chunk internal layout. 3-stage ring, prefetch distance 2, wait_group 1.
// Sub-chunk (36864 B): Ahi[0) Alo[9216) B0h[18432) B0l[23040) B1h[27648) B1l[32256).
#define NSTAGE 3
#define SUBSTG 36864
#define PSTG (2 * SUBSTG)   /* 73728 */
#define PAS 72

__global__ void __launch_bounds__(512, 1) lstm_persist(const float* __restrict__ b1) {
    extern __shared__ __align__(16) char sm[];
    const int tid  = threadIdx.x;
    const int lane = tid & 31;
    const int warp = tid >> 5;
    const int wm = warp >> 2;           // 0..3 -> m = wm*16
    const int wn = warp & 3;            // 0..3 -> n = wn*8
    const int nb = blockIdx.x;

    const uint32_t smb = (uint32_t)__cvta_generic_to_shared(sm);
    const int gq = lane >> 3, jq = lane & 7;
    const uint32_t aA  = (uint32_t)(((wm * 16 + (gq & 1) * 8 + jq) * PAS + (gq >> 1) * 8) * 2);
    const uint32_t aB0 = 18432u + (uint32_t)(((wn * 8 + jq) * PAS + (gq & 1) * 8) * 2);
    const uint32_t aB1 = aB0 + 9216u;

    // loader mapping (512 threads) within one 64-K sub-chunk
    const int lr = tid >> 3;            // A row 0..63 (batch)
    const int lc = (tid & 7) * 8;       // A col (bf16): one 16B chunk
    const uint32_t dAh = (uint32_t)((lr * PAS + lc) * 2);
    const uint32_t dAl = dAh + 9216;
    const int arow = lr * H_ + lc;
    const bool half0 = (tid < 256);     // threads 0-255: B0; 256-511: B1
    const int br = (tid & 255) >> 3;    // B row 0..31 (gate col)
    const int bc = (tid & 7) * 8;
    const uint32_t dB = (uint32_t)(18432 + (br * PAS + bc) * 2);  // B0h dest base
    const bf16* W0bh = g_A0hi + (size_t)(nb * 32 + br) * H_ + bc;
    const bf16* W0bl = g_A0lo + (size_t)(nb * 32 + br) * H_ + bc;
    const bf16* W1bh = g_A1hi + (size_t)(nb * 32 + br) * (2 * H_) + bc;
    const bf16* W1bl = g_A1lo + (size_t)(nb * 32 + br) * (2 * H_) + bc;

    // epilogue: each thread owns one (b, hl) per layer
    const int hl = tid & 7, bep = tid >> 3;   // bep 0..63
    const int hg = nb * 8 + hl;
    float c0reg = 0.f, c1reg = 0.f;
    const float bz0 = b1[hg], bz1 = b1[H_ + hg], bz2 = b1[2 * H_ + hg], bz3 = b1[3 * H_ + hg];

    for (int tick = 0; tick <= T_; tick++) {
        const int  w0   = tick & 1;                 // L0 writes h0[w0]; L1 writes h1[w0^1]
        const bool doL0 = (tick < T_);
        const bool doL1 = (tick >= 1);
        const int  itE  = doL1 ? 16 : 8;            // macro-iterations this tick
        const bf16* hRh  = g_h0hi[w0 ^ 1];          // h0(tick-1)
        const bf16* hRl  = g_h0lo[w0 ^ 1];
        const bf16* h1Rh = g_h1hi[w0];              // h1(tick-2)
        const bf16* h1Rl = g_h1lo[w0];

        // load macro-iter it (K=128) into stage stg (two 64-K sub-chunks)
        auto issue = [&](int it, int stg) {
            uint32_t stbase = smb + (uint32_t)stg * PSTG;
#pragma unroll
            for (int c = 0; c < 2; c++) {
                uint32_t st = stbase + (uint32_t)c * SUBSTG;
                if (it < 8) {
                    int kk = it * 128 + c * 64;
                    cp16(st + dAh, hRh + arow + kk);
                    cp16(st + dAl, hRl + arow + kk);
                    if (half0) { if (doL0) { cp16(st + dB, W0bh + kk);        cp16(st + dB + 4608, W0bl + kk); } }
                    else       { if (doL1) { cp16(st + dB + 9216, W1bh + kk); cp16(st + dB + 13824, W1bl + kk); } }
                } else {
                    int kk = (it - 8) * 128 + c * 64;
                    cp16(st + dAh, h1Rh + arow + kk);
                    cp16(st + dAl, h1Rl + arow + kk);
                    if (!half0) { cp16(st + dB + 9216, W1bh + H_ + kk); cp16(st + dB + 13824, W1bl + H_ + kk); }
                }
            }
        };

        // pipeline prologue: 2 stages ahead
#pragma unroll
        for (int j = 0; j < 2; j++) { issue(j, j); asm volatile("cp.async.commit_group;\n"); }

        // early prefetch of L0 epilogue operand (DRAM-resident Z0x)
        float4 zx0;
        if (doL0)
            zx0 = *(const float4*)&g_Z0x[((size_t)tick * 64 + bep) * NG + nb * 32 + hl * 4];

        float a0[4] = {}, a1[4] = {};
        int s = 0, sn = 2;
        for (int it = 0; it < itE; it++) {
            asm volatile("cp.async.wait_group 1;\n");
            __syncthreads();                        // stage s (macro-iter it) ready
            int nx = it + 2;
            if (nx < itE) issue(nx, sn);
            asm volatile("cp.async.commit_group;\n");
            const uint32_t stbase = smb + (uint32_t)s * PSTG;
            if (it < 8) {
#pragma unroll
                for (int c = 0; c < 2; c++) {
                    const uint32_t st = stbase + (uint32_t)c * SUBSTG;
#pragma unroll
                    for (int kk = 0; kk < 64; kk += 16) {
                        uint32_t ah[4], al[4];
                        ldsm4(ah, st + aA + kk * 2);
                        ldsm4(al, st + aA + 9216 + kk * 2);
                        if (doL0) {
                            uint32_t bh[2], bl[2];
                            ldsm2(bh, st + aB0 + kk * 2);
                            ldsm2(bl, st + aB0 + 4608 + kk * 2);
                            mma_bf16(a0, ah, bh); mma_bf16(a0, al, bh); mma_bf16(a0, ah, bl);
                        }
                        if (doL1) {
                            uint32_t bh[2], bl[2];
                            ldsm2(bh, st + aB1 + kk * 2);
                            ldsm2(bl, st + aB1 + 4608 + kk * 2);
                            mma_bf16(a1, ah, bh); mma_bf16(a1, al, bh); mma_bf16(a1, ah, bl);
                        }
                    }
                }
            } else {
#pragma unroll
                for (int c = 0; c < 2; c++) {
                    const uint32_t st = stbase + (uint32_t)c * SUBSTG;
#pragma unroll
                    for (int kk = 0; kk < 64; kk += 16) {
                        uint32_t ah[4], al[4], bh[2], bl[2];
                        ldsm4(ah, st + aA + kk * 2);
                        ldsm4(al, st + aA + 9216 + kk * 2);
                        ldsm2(bh, st + aB1 + kk * 2);
                        ldsm2(bl, st + aB1 + 4608 + kk * 2);
                        mma_bf16(a1, ah, bh); mma_bf16(a1, al, bh); mma_bf16(a1, ah, bl);
                    }
                }
            }
            s  = (s == NSTAGE - 1) ? 0 : s + 1;
            sn = (sn == NSTAGE - 1) ? 0 : sn + 1;
        }
        __syncthreads();

        // park both z tiles (64x32 each) so each thread gathers all 4 gates of one (b,h)
        float* z0 = (float*)sm;
        float* z1 = (float*)(sm + 8448);
        {
            int r = wm * 16 + (lane >> 2), c = wn * 8 + (lane & 3) * 2;
            z0[r * 33 + c]           = a0[0]; z0[r * 33 + c + 1]       = a0[1];
            z0[(r + 8) * 33 + c]     = a0[2]; z0[(r + 8) * 33 + c + 1] = a0[3];
            z1[r * 33 + c]           = a1[0]; z1[r * 33 + c + 1]       = a1[1];
            z1[(r + 8) * 33 + c]     = a1[2]; z1[(r + 8) * 33 + c + 1] = a1[3];
        }
        __syncthreads();

        if (doL0) {   // L0 epilogue: t = tick, write h0[w0]
            float zg = z0[bep * 33 + hl * 4 + 0] + zx0.x;
            float zi = z0[bep * 33 + hl * 4 + 1] + zx0.y;
            float zf = z0[bep * 33 + hl * 4 + 2] + zx0.z;
            float zo = z0[bep * 33 + hl * 4 + 3] + zx0.w;
            float gt = tanhf(zg);
            float ig = 1.f / (1.f + __expf(-zi));
            float fg = 1.f / (1.f + __expf(-zf));
            float og = 1.f / (1.f + __expf(-zo));
            float cn = gt * ig + c0reg * fg;
            c0reg = cn;
            float hn = tanhf(cn) * og;
            bf16 hh = __float2bfloat16(hn);
            g_h0hi[w0][bep * H_ + hg] = hh;
            g_h0lo[w0][bep * H_ + hg] = __float2bfloat16(hn - __bfloat162float(hh));
        }
        if (doL1) {   // L1 epilogue: t' = tick-1, write h1[w0^1]
            float zg = z1[bep * 33 + hl * 4 + 0] + bz0;
            float zi = z1[bep * 33 + hl * 4 + 1] + bz1;
            float zf = z1[bep * 33 + hl * 4 + 2] + bz2;
            float zo = z1[bep * 33 + hl * 4 + 3] + bz3;
            float gt = tanhf(zg);
            float ig = 1.f / (1.f + __expf(-zi));
            float fg = 1.f / (1.f + __expf(-zf));
            float og = 1.f / (1.f + __expf(-zo));
            float cn = gt * ig + c1reg * fg;
            c1reg = cn;
            float hn = tanhf(cn) * og;
            bf16 hh = __float2bfloat16(hn);
            g_h1hi[w0 ^ 1][bep * H_ + hg] = hh;
            g_h1lo[w0 ^ 1][bep * H_ + hg] = __float2bfloat16(hn - __bfloat162float(hh));
            if (tick - 1 == T_ - 1) g_h1f[bep * H_ + hg] = hn;
        }

        // ---- global barrier (monotonic counter; zeroed by prep each launch) ----
        __syncthreads();
        if (tid == 0) {
            __threadfence();
            atomicAdd(&g_bar, 1u);
            unsigned target = (unsigned)(tick + 1) * NCTA;
            while (*((volatile unsigned*)&g_bar) < target) __nanosleep(32);
            __threadfence();
        }
        __syncthreads();
    }
}

// out = h1(T-1) @ Wo + bo   (one block per batch row)
__global__ __launch_bounds__(256) void out_kernel(const float* __restrict__ Wo,
                                                  const float* __restrict__ bo,
                                                  float* __restrict__ out) {
    __shared__ float hs[H_];
    int b = blockIdx.x;
    for (int k = threadIdx.x; k < H_; k += 256) hs[k] = g_h1f[b * H_ + k];
    __syncthreads();
    for (int c = threadIdx.x; c < C_; c += 256) {
        float a = bo[c];
#pragma unroll 8
        for (int k = 0; k < H_; k++) a += hs[k] * Wo[k * C_ + c];
        out[b * C_ + c] = a;
    }
}

extern "C" void kernel_launch(void* const* d_in, const int* in_sizes, int n_in,
                              void* d_out, int out_size) {
    const float* x   = (const float*)d_in[0];
    const float* W0x = (const float*)d_in[1];
    const float* W0h = (const float*)d_in[2];
    const float* b0  = (const float*)d_in[3];
    const float* W1x = (const float*)d_in[4];
    const float* W1h = (const float*)d_in[5];
    const float* b1  = (const float*)d_in[6];
    const float* Wo  = (const float*)d_in[7];
    const float* bo  = (const float*)d_in[8];
    float* out = (float*)d_out;

    cudaFuncSetAttribute(lstm_persist, cudaFuncAttributeMaxDynamicSharedMemorySize,
                         NSTAGE * PSTG);

    // lstm_persist stays our 4th launch (ncu -s 5 -c 1 captures it)
    prep_kernel<<<18560, 256>>>(x, W0x, W0h, W1x, W1h);          // #1
    {
        dim3 g(NG / 64, T_);
        gemm_x_kernel<<<g, 256>>>(b0);                           // #2
    }
    dummy_kernel<<<1, 32>>>();                                   // #3
    lstm_persist<<<NCTA, 512, NSTAGE * PSTG>>>(b1);              // #4  <- profiled
    out_kernel<<<B_, 256>>>(Wo, bo, out);                        // #5
}